// round 2
// baseline (speedup 1.0000x reference)
#include <cuda_runtime.h>
#include <cuda_bf16.h>

// GraphConvOp: out[b,t,v,f] = sum_e [rows[e]==v] * vals[e] * in[b,t,cols[e],f]
// B=2, T=16 (BT=32), V=10000, F=32, NNZ=160000. rows sorted -> CSR segments.
// L2-bound gather: intrinsic x-traffic = NNZ*BT*F*4B = 655MB @ L2 (~58us floor).

#define V_NODES 10000
#define F_DIM   32
#define BT      32
#define EDGE_CHUNK 128

// Scratch (no cudaMalloc allowed): CSR row pointer.
__device__ int g_row_ptr[V_NODES + 1];

// --- Kernel 1: initialize row_ptr to nnz (handles trailing empty rows) ---
__global__ void init_rowptr_kernel(int nnz) {
    int i = blockIdx.x * blockDim.x + threadIdx.x;
    if (i <= V_NODES) g_row_ptr[i] = nnz;
}

// --- Kernel 2: boundary scan on sorted rows -> row_ptr ---
__global__ void build_rowptr_kernel(const int* __restrict__ rows, int nnz) {
    int e = blockIdx.x * blockDim.x + threadIdx.x;
    if (e >= nnz) return;
    int r     = rows[e];
    int rprev = (e == 0) ? -1 : rows[e - 1];
    // only threads at a row transition write; each slot written exactly once
    for (int i = rprev + 1; i <= r; ++i) g_row_ptr[i] = e;
}

// --- Kernel 3: gather-accumulate SpMM ---
// grid = V blocks, 256 threads (8 warps). Warp w owns bt-slices [4w, 4w+4).
// lane: bt_sub = lane>>3, f4 = lane&7 (8 float4 lanes cover F=32).
// Per edge a warp issues 4 coalesced 128B gathers (all L2-resident).
// cols/vals staged in SMEM once per block (kills the 8x per-warp redundancy,
// ~82MB of L2 traffic = ~12% of total).
__global__ __launch_bounds__(256, 8)
void spmm_kernel(const float* __restrict__ x,
                 const float* __restrict__ vals,
                 const int*   __restrict__ cols,
                 float*       __restrict__ out)
{
    __shared__ int   s_cols[EDGE_CHUNK];
    __shared__ float s_vals[EDGE_CHUNK];

    const int v    = blockIdx.x;
    const int warp = threadIdx.x >> 5;
    const int lane = threadIdx.x & 31;
    const int bt   = warp * 4 + (lane >> 3);
    const int f4   = lane & 7;

    const int start = g_row_ptr[v];
    const int end   = g_row_ptr[v + 1];

    // x viewed as float4: element (bt, col, f4) at (bt*V + col)*8 + f4
    const float4* __restrict__ xb =
        reinterpret_cast<const float4*>(x) + (size_t)bt * V_NODES * 8 + f4;

    float4 acc = make_float4(0.f, 0.f, 0.f, 0.f);

    for (int base = start; base < end; base += EDGE_CHUNK) {
        const int n = min(EDGE_CHUNK, end - base);
        // cooperative stage of this row's edge list (usually one pass: deg~16)
        for (int i = threadIdx.x; i < n; i += 256) {
            s_cols[i] = cols[base + i];
            s_vals[i] = vals[base + i];
        }
        __syncthreads();

        int i = 0;
        // 4-edge unroll: batch the 4 independent gathers for MLP, then FMA.
        for (; i + 4 <= n; i += 4) {
            int   c0 = s_cols[i+0], c1 = s_cols[i+1], c2 = s_cols[i+2], c3 = s_cols[i+3];
            float w0 = s_vals[i+0], w1 = s_vals[i+1], w2 = s_vals[i+2], w3 = s_vals[i+3];
            float4 x0 = __ldg(xb + (size_t)c0 * 8);
            float4 x1 = __ldg(xb + (size_t)c1 * 8);
            float4 x2 = __ldg(xb + (size_t)c2 * 8);
            float4 x3 = __ldg(xb + (size_t)c3 * 8);

            acc.x = fmaf(w0, x0.x, acc.x); acc.y = fmaf(w0, x0.y, acc.y);
            acc.z = fmaf(w0, x0.z, acc.z); acc.w = fmaf(w0, x0.w, acc.w);
            acc.x = fmaf(w1, x1.x, acc.x); acc.y = fmaf(w1, x1.y, acc.y);
            acc.z = fmaf(w1, x1.z, acc.z); acc.w = fmaf(w1, x1.w, acc.w);
            acc.x = fmaf(w2, x2.x, acc.x); acc.y = fmaf(w2, x2.y, acc.y);
            acc.z = fmaf(w2, x2.z, acc.z); acc.w = fmaf(w2, x2.w, acc.w);
            acc.x = fmaf(w3, x3.x, acc.x); acc.y = fmaf(w3, x3.y, acc.y);
            acc.z = fmaf(w3, x3.z, acc.z); acc.w = fmaf(w3, x3.w, acc.w);
        }
        for (; i < n; ++i) {
            int   c  = s_cols[i];
            float w  = s_vals[i];
            float4 xx = __ldg(xb + (size_t)c * 8);
            acc.x = fmaf(w, xx.x, acc.x); acc.y = fmaf(w, xx.y, acc.y);
            acc.z = fmaf(w, xx.z, acc.z); acc.w = fmaf(w, xx.w, acc.w);
        }
        __syncthreads();
    }

    float4* __restrict__ ob =
        reinterpret_cast<float4*>(out) + ((size_t)bt * V_NODES + v) * 8 + f4;
    *ob = acc;  // zero-degree rows write zeros (d_out is poisoned, must init)
}

extern "C" void kernel_launch(void* const* d_in, const int* in_sizes, int n_in,
                              void* d_out, int out_size) {
    const float* x    = (const float*)d_in[0];   // inputs [B,T,V,F] f32
    const float* vals = (const float*)d_in[1];   // L_vals [NNZ] f32
    const int*   rows = (const int*)  d_in[2];   // L_rows [NNZ] i32 (sorted)
    const int*   cols = (const int*)  d_in[3];   // L_cols [NNZ] i32
    float*       out  = (float*)d_out;
    const int nnz = in_sizes[1];

    init_rowptr_kernel<<<(V_NODES + 1 + 255) / 256, 256>>>(nnz);
    build_rowptr_kernel<<<(nnz + 255) / 256, 256>>>(rows, nnz);
    spmm_kernel<<<V_NODES, 256>>>(x, vals, cols, out);
}